// round 17
// baseline (speedup 1.0000x reference)
#include <cuda_runtime.h>
#include <cuda_bf16.h>
#include <mma.h>
#include <math.h>

using namespace nvcuda;

// Problem constants
#define BATCH   4
#define HH      64
#define WW      64
#define CIN     128
#define FILTERS 128
#define HEADS   8
#define HSIZE   16
#define K0      7
#define K1      7
#define KD      49
#define NPIX    (BATCH*HH*WW)      // 16384
#define NQKV    384                 // q|k|v concat

typedef unsigned long long ull;
typedef unsigned int u32;

// packed f32x2 helpers (sm_100+)
#define FMA2(d, a, b)   asm("fma.rn.f32x2 %0, %1, %2, %0;" : "+l"(d) : "l"(a), "l"(b))
#define MUL2(d, a, b)   asm("mul.rn.f32x2 %0, %1, %2;"     : "=l"(d) : "l"(a), "l"(b))
#define ADD2(d, a, b)   asm("add.rn.f32x2 %0, %1, %2;"     : "=l"(d) : "l"(a), "l"(b))
#define PACK2(d, x, y)  asm("mov.b64 %0, {%1, %2};" : "=l"(d) : "f"(x), "f"(y))
#define UNPK2(lo, hi, s) asm("mov.b64 {%0, %1}, %2;" : "=f"(lo), "=f"(hi) : "l"(s))

__device__ float g_QKV[NPIX * NQKV];

// pre-split bf16 hi/lo storage (4 bf16 per ull)
#define XCHUNKS (NPIX * CIN / 4)          // 524288
#define WCHUNKS (3 * CIN * FILTERS / 4)   // 12288
#define NXP (XCHUNKS / 2)
#define NWP (WCHUNKS / 2)
__device__ ull g_Xhi[XCHUNKS];
__device__ ull g_Xlo[XCHUNKS];
__device__ ull g_Whi[WCHUNKS];
__device__ ull g_Wlo[WCHUNKS];

__device__ __forceinline__ void split4(float4 v, ull& hi, ull& lo) {
    __nv_bfloat16 h0 = __float2bfloat16_rn(v.x);
    __nv_bfloat16 h1 = __float2bfloat16_rn(v.y);
    __nv_bfloat16 h2 = __float2bfloat16_rn(v.z);
    __nv_bfloat16 h3 = __float2bfloat16_rn(v.w);
    __nv_bfloat16 l0 = __float2bfloat16_rn(v.x - __bfloat162float(h0));
    __nv_bfloat16 l1 = __float2bfloat16_rn(v.y - __bfloat162float(h1));
    __nv_bfloat16 l2 = __float2bfloat16_rn(v.z - __bfloat162float(h2));
    __nv_bfloat16 l3 = __float2bfloat16_rn(v.w - __bfloat162float(h3));
    unsigned short s0 = *(unsigned short*)&h0, s1 = *(unsigned short*)&h1;
    unsigned short s2 = *(unsigned short*)&h2, s3 = *(unsigned short*)&h3;
    hi = (ull)s0 | ((ull)s1 << 16) | ((ull)s2 << 32) | ((ull)s3 << 48);
    s0 = *(unsigned short*)&l0; s1 = *(unsigned short*)&l1;
    s2 = *(unsigned short*)&l2; s3 = *(unsigned short*)&l3;
    lo = (ull)s0 | ((ull)s1 << 16) | ((ull)s2 << 32) | ((ull)s3 << 48);
}

// ---------------------------------------------------------------------------
// Kernel 0: pre-split X, Wq, Wk, Wv (R16 proven).
// ---------------------------------------------------------------------------
__global__ __launch_bounds__(256)
void presplit_kernel(const float* __restrict__ X,
                     const float* __restrict__ Wq,
                     const float* __restrict__ Wk,
                     const float* __restrict__ Wv)
{
    const int t = blockIdx.x * 256 + threadIdx.x;
    if (t < NXP) {
        const int c0 = 2 * t;
        float4 v0 = ((const float4*)X)[c0];
        float4 v1 = ((const float4*)X)[c0 + 1];
        ull h0, l0, h1, l1;
        split4(v0, h0, l0);
        split4(v1, h1, l1);
        *(ulonglong2*)&g_Xhi[c0] = make_ulonglong2(h0, h1);
        *(ulonglong2*)&g_Xlo[c0] = make_ulonglong2(l0, l1);
    } else {
        const int w = t - NXP;
        if (w < NWP) {
            const int c0 = 2 * w;
            const int kind = c0 / (WCHUNKS / 3);
            const int off  = c0 % (WCHUNKS / 3);
            const float* W = (kind == 0) ? Wq : (kind == 1) ? Wk : Wv;
            float4 v0 = ((const float4*)W)[off];
            float4 v1 = ((const float4*)W)[off + 1];
            ull h0, l0, h1, l1;
            split4(v0, h0, l0);
            split4(v1, h1, l1);
            *(ulonglong2*)&g_Whi[c0] = make_ulonglong2(h0, h1);
            *(ulonglong2*)&g_Wlo[c0] = make_ulonglong2(l0, l1);
        }
    }
}

// ---------------------------------------------------------------------------
// Kernel A: persistent-A bf16x3 WMMA GEMM (R16 proven).
// ---------------------------------------------------------------------------
#define TLD 136
#define TILE_E (128 * TLD)
#define A_REGION (2 * TILE_E * 2)          // 69632 B
#define CLD 132
#define GEMM_SMEM (4 * TILE_E * 2)         // 139264 B

__global__ __launch_bounds__(256)
void qkv_gemm_kernel(const float* __restrict__ bq,
                     const float* __restrict__ bk,
                     const float* __restrict__ bv,
                     float* __restrict__ QKV)
{
    extern __shared__ __align__(16) char smem[];
    __nv_bfloat16* Ahi = (__nv_bfloat16*)smem;
    __nv_bfloat16* Alo = Ahi + TILE_E;
    __nv_bfloat16* Bhi = Alo + TILE_E;
    __nv_bfloat16* Blo = Bhi + TILE_E;
    float* Cst = (float*)(smem + A_REGION);

    const int bm = blockIdx.x * 128;
    const int tid = threadIdx.x;
    const int wid = tid >> 5;
    const int warp_m = wid & 3;
    const int warp_n = wid >> 2;

#pragma unroll
    for (int l = 0; l < 8; l++) {
        const int idx = tid + l * 256;
        const int r = idx >> 4, c = idx & 15;
        const int gsrc = (bm + r) * 16 + c;
        *(uint4*)&Ahi[r * TLD + c * 8] = ((const uint4*)g_Xhi)[gsrc];
        *(uint4*)&Alo[r * TLD + c * 8] = ((const uint4*)g_Xlo)[gsrc];
    }

    for (int kind = 0; kind < 3; kind++) {
        const float* bias = (kind == 0) ? bq : (kind == 1) ? bk : bv;

#pragma unroll
        for (int l = 0; l < 8; l++) {
            const int idx = tid + l * 256;
            const int r = idx >> 4, c = idx & 15;
            const int wsrc = kind * 2048 + r * 16 + c;
            *(uint4*)&Bhi[r * TLD + c * 8] = ((const uint4*)g_Whi)[wsrc];
            *(uint4*)&Blo[r * TLD + c * 8] = ((const uint4*)g_Wlo)[wsrc];
        }
        __syncthreads();

        wmma::fragment<wmma::accumulator, 16, 16, 16, float> acc[2][4];
#pragma unroll
        for (int i = 0; i < 2; i++)
#pragma unroll
            for (int j = 0; j < 4; j++) wmma::fill_fragment(acc[i][j], 0.f);

#pragma unroll
        for (int ks = 0; ks < CIN; ks += 16) {
            wmma::fragment<wmma::matrix_a, 16, 16, 16, __nv_bfloat16, wmma::row_major> ah[2], al[2];
            wmma::fragment<wmma::matrix_b, 16, 16, 16, __nv_bfloat16, wmma::row_major> bh[4], bl[4];
#pragma unroll
            for (int i = 0; i < 2; i++) {
                const int row = warp_m * 32 + i * 16;
                wmma::load_matrix_sync(ah[i], Ahi + row * TLD + ks, TLD);
                wmma::load_matrix_sync(al[i], Alo + row * TLD + ks, TLD);
            }
#pragma unroll
            for (int j = 0; j < 4; j++) {
                const int col = warp_n * 64 + j * 16;
                wmma::load_matrix_sync(bh[j], Bhi + ks * TLD + col, TLD);
                wmma::load_matrix_sync(bl[j], Blo + ks * TLD + col, TLD);
            }
#pragma unroll
            for (int i = 0; i < 2; i++)
#pragma unroll
                for (int j = 0; j < 4; j++) {
                    wmma::mma_sync(acc[i][j], ah[i], bh[j], acc[i][j]);
                    wmma::mma_sync(acc[i][j], al[i], bh[j], acc[i][j]);
                    wmma::mma_sync(acc[i][j], ah[i], bl[j], acc[i][j]);
                }
        }

        __syncthreads();
#pragma unroll
        for (int i = 0; i < 2; i++)
#pragma unroll
            for (int j = 0; j < 4; j++)
                wmma::store_matrix_sync(Cst + (warp_m * 32 + i * 16) * CLD + warp_n * 64 + j * 16,
                                        acc[i][j], CLD, wmma::mem_row_major);
        __syncthreads();

#pragma unroll
        for (int l = 0; l < 16; l++) {
            const int idx = tid + l * 256;
            const int r = idx >> 5, c4 = idx & 31;
            float4 v = *(float4*)&Cst[r * CLD + c4 * 4];
            v.x += bias[c4 * 4 + 0];
            v.y += bias[c4 * 4 + 1];
            v.z += bias[c4 * 4 + 2];
            v.w += bias[c4 * 4 + 3];
            *(float4*)(QKV + (size_t)(bm + r) * NQKV + kind * 128 + c4 * 4) = v;
        }
        __syncthreads();
    }
}

// ---------------------------------------------------------------------------
// Kernel B: pixel-pair attention, interleaved K|V layout (PSTR=36) + 2-deep
// software pipeline over the 56 positions.
// smem = 484 * 36 * 4 = 69696 B -> 3 blocks/SM (12 warps).
// K at slot+0..15, V at slot+16..31 floats. 8-lane LDS.128 phase banks
// 4l..4l+3 (stride 144 B): conflict-free, same pattern as proven kernel.
// ---------------------------------------------------------------------------
#define TILE    16
#define HALO    22
#define NHALO   (HALO*HALO)     // 484
#define PSTRKV  36
#define ATTN_SMEM (NHALO * PSTRKV * 4)   // 69696 B

__device__ __forceinline__ void load_pos(const float* buf, int eoff,
                                         ull* kr, ull* vr) {
    ulonglong2 t;
    t = *(const ulonglong2*)(buf + eoff +  0); kr[0]=t.x; kr[1]=t.y;
    t = *(const ulonglong2*)(buf + eoff +  4); kr[2]=t.x; kr[3]=t.y;
    t = *(const ulonglong2*)(buf + eoff +  8); kr[4]=t.x; kr[5]=t.y;
    t = *(const ulonglong2*)(buf + eoff + 12); kr[6]=t.x; kr[7]=t.y;
    t = *(const ulonglong2*)(buf + eoff + 16); vr[0]=t.x; vr[1]=t.y;
    t = *(const ulonglong2*)(buf + eoff + 20); vr[2]=t.x; vr[3]=t.y;
    t = *(const ulonglong2*)(buf + eoff + 24); vr[4]=t.x; vr[5]=t.y;
    t = *(const ulonglong2*)(buf + eoff + 28); vr[6]=t.x; vr[7]=t.y;
}

__device__ __forceinline__ void attn_step(const ull* q, const ull* kr, const ull* vr,
                                          ull* o, float& sum, float qeval) {
    ull m0, m1;
    MUL2(m0, q[0], kr[0]);
    MUL2(m1, q[1], kr[1]);
    FMA2(m0, q[2], kr[2]);
    FMA2(m1, q[3], kr[3]);
    FMA2(m0, q[4], kr[4]);
    FMA2(m1, q[5], kr[5]);
    FMA2(m0, q[6], kr[6]);
    FMA2(m1, q[7], kr[7]);
    ADD2(m0, m0, m1);
    float lo, hi;
    UNPK2(lo, hi, m0);
    const float e = __expf(lo + hi + qeval);
    sum += e;
    ull ep; PACK2(ep, e, e);
#pragma unroll
    for (int j = 0; j < 8; j++) FMA2(o[j], ep, vr[j]);
}

__global__ __launch_bounds__(128, 3)
void attn_kernel(const float* __restrict__ QKV,
                 const float* __restrict__ emb0,   // [64,7]
                 const float* __restrict__ emb1,   // [64,7]
                 float* __restrict__ out)
{
    extern __shared__ float sbuf[];

    const int tid = threadIdx.x;
    const int px  = tid & 15;
    const int yp  = tid >> 4;          // 0..7
    const int tx0 = (blockIdx.x & 3) * TILE;
    const int ty0 = (blockIdx.x >> 2) * TILE;
    const int b   = blockIdx.y;
    const int h   = blockIdx.z;

    // ---- load K and V halos interleaved (zero-filled OOB) ----
    {
        const int koff = FILTERS + h * HSIZE;
        const int voff = 2 * FILTERS + h * HSIZE;
#pragma unroll
        for (int i = tid; i < NHALO * 4; i += 128) {
            const int hp = i >> 2, c4 = i & 3;
            const int hy = hp / HALO, hx = hp % HALO;
            const int sy = ty0 + hy - 3, sx = tx0 + hx - 3;
            float4 kv = make_float4(0.f, 0.f, 0.f, 0.f);
            float4 vv = make_float4(0.f, 0.f, 0.f, 0.f);
            if ((unsigned)sy < HH && (unsigned)sx < WW) {
                const float* base = QKV + (size_t)(((b * HH) + sy) * WW + sx) * NQKV;
                kv = *(const float4*)(base + koff + c4 * 4);
                vv = *(const float4*)(base + voff + c4 * 4);
            }
            *(float4*)&sbuf[hp * PSTRKV + c4 * 4]      = kv;
            *(float4*)&sbuf[hp * PSTRKV + 16 + c4 * 4] = vv;
        }
    }

    const int y0   = ty0 + 2 * yp;
    const int pix0 = ((b * HH) + y0) * WW + (tx0 + px);
    const int pix1 = pix0 + WW;

    ull q0[8], q1[8];
    {
        const ulonglong2* qp0 = (const ulonglong2*)(QKV + (size_t)pix0 * NQKV + h * HSIZE);
        const ulonglong2* qp1 = (const ulonglong2*)(QKV + (size_t)pix1 * NQKV + h * HSIZE);
#pragma unroll
        for (int j = 0; j < 4; j++) {
            ulonglong2 t0 = qp0[j];
            ulonglong2 t1 = qp1[j];
            q0[2*j] = t0.x; q0[2*j+1] = t0.y;
            q1[2*j] = t1.x; q1[2*j+1] = t1.y;
        }
    }

    const bool use0 = (h < 4);
    float qe0[7], qe1[7];
    {
        const float* etab = use0 ? (emb0 + h * HSIZE * K0)
                                 : (emb1 + (h * HSIZE - 64) * K1);
        float qf0[16], qf1[16];
#pragma unroll
        for (int j = 0; j < 8; j++) {
            UNPK2(qf0[2*j], qf0[2*j+1], q0[j]);
            UNPK2(qf1[2*j], qf1[2*j+1], q1[j]);
        }
#pragma unroll
        for (int r = 0; r < 7; r++) {
            float s0 = 0.f, s1 = 0.f;
#pragma unroll
            for (int d = 0; d < 16; d++) {
                const float e = etab[d * 7 + r];
                s0 += qf0[d] * e;
                s1 += qf1[d] * e;
            }
            qe0[r] = s0;
            qe1[r] = s1;
        }
    }

    __syncthreads();

    // ---- pipelined one-pass softmax-attention over 8x7 union window ----
    float sum0 = 0.f, sum1 = 0.f;
    ull o0[8], o1[8];
#pragma unroll
    for (int j = 0; j < 8; j++) { o0[j] = 0ull; o1[j] = 0ull; }

    const int base_off = (2 * yp * HALO + px) * PSTRKV;
    ull kr[2][8], vr[2][8];
    load_pos(sbuf, base_off, kr[0], vr[0]);

#pragma unroll
    for (int p = 0; p < 56; p++) {
        const int cur = p & 1;
        if (p < 55) {
            const int pn  = p + 1;
            const int drn = pn / 7, djn = pn % 7;
            load_pos(sbuf, base_off + (drn * HALO + djn) * PSTRKV,
                     kr[cur ^ 1], vr[cur ^ 1]);
        }
        const int dr = p / 7, dj = p % 7;
        if (dr < 7)
            attn_step(q0, kr[cur], vr[cur], o0, sum0, use0 ? qe0[dr]   : qe0[dj]);
        if (dr > 0)
            attn_step(q1, kr[cur], vr[cur], o1, sum1, use0 ? qe1[dr-1] : qe1[dj]);
    }

    const float inv0 = 1.f / sum0;
    const float inv1 = 1.f / sum1;
    float* op0 = out + (size_t)pix0 * FILTERS + h * HSIZE;
    float* op1 = out + (size_t)pix1 * FILTERS + h * HSIZE;
#pragma unroll
    for (int j = 0; j < 4; j++) {
        float a0, a1, b0, b1;
        UNPK2(a0, a1, o0[2*j]);
        UNPK2(b0, b1, o0[2*j+1]);
        float4 r0 = make_float4(a0*inv0, a1*inv0, b0*inv0, b1*inv0);
        *(float4*)(op0 + j*4) = r0;
        UNPK2(a0, a1, o1[2*j]);
        UNPK2(b0, b1, o1[2*j+1]);
        float4 r1 = make_float4(a0*inv1, a1*inv1, b0*inv1, b1*inv1);
        *(float4*)(op1 + j*4) = r1;
    }
}

// ---------------------------------------------------------------------------
extern "C" void kernel_launch(void* const* d_in, const int* in_sizes, int n_in,
                              void* d_out, int out_size)
{
    const float* x    = (const float*)d_in[0];
    const float* Wq   = (const float*)d_in[1];
    const float* bq   = (const float*)d_in[2];
    const float* Wk   = (const float*)d_in[3];
    const float* bk   = (const float*)d_in[4];
    const float* Wv   = (const float*)d_in[5];
    const float* bv   = (const float*)d_in[6];
    const float* emb0 = (const float*)d_in[7];
    const float* emb1 = (const float*)d_in[8];
    float* out = (float*)d_out;

    float* qkv = nullptr;
    cudaGetSymbolAddress((void**)&qkv, g_QKV);

    cudaFuncSetAttribute(qkv_gemm_kernel,
                         cudaFuncAttributeMaxDynamicSharedMemorySize, GEMM_SMEM);
    cudaFuncSetAttribute(attn_kernel,
                         cudaFuncAttributeMaxDynamicSharedMemorySize, ATTN_SMEM);

    const int total_threads = NXP + NWP;
    presplit_kernel<<<(total_threads + 255) / 256, 256>>>(x, Wq, Wk, Wv);

    qkv_gemm_kernel<<<128, 256, GEMM_SMEM>>>(bq, bk, bv, qkv);

    dim3 ga(16, BATCH, HEADS);                 // 512 blocks
    attn_kernel<<<ga, 128, ATTN_SMEM>>>(qkv, emb0, emb1, out);
}